// round 1
// baseline (speedup 1.0000x reference)
#include <cuda_runtime.h>
#include <cstdint>

#define B_   128
#define S_   1024
#define I_   128
#define H_   256
#define OFF_SLOPE 0.001f

// ---------------- device scratch (static, no allocations) ----------------
__device__ __align__(16) float g_G[134217728];      // [B*S][1024] = 512 MB
__device__ __align__(16) float g_hbuf[2][B_ * H_];  // double-buffered h exchange
__device__ unsigned g_cnt[16];                      // per-group barrier counters

// ---------------- init: reset counters + h0 = 0 (every launch/replay) ----
__global__ void init_k() {
    unsigned t = blockIdx.x * blockDim.x + threadIdx.x;
    if (t < 16) g_cnt[t] = 0u;
    for (unsigned i = t; i < 2u * B_ * H_; i += gridDim.x * blockDim.x)
        ((float*)g_hbuf)[i] = 0.f;
}

// ---------------- phase A: G = x @ W + bias  (fp32 tiled SGEMM) ----------
// M=131072, K=128, N=1024. Block tile 64(M) x 128(N), BK=32, 256 threads,
// thread tile 8x4 (A-frag broadcast per warp, B-frag conflict-free).
__global__ __launch_bounds__(256) void gemm_xw(const float* __restrict__ X,
                                               const float* __restrict__ Wm,
                                               const float* __restrict__ bias) {
    __shared__ __align__(16) float As[32][68];    // [k][m] transposed, padded
    __shared__ __align__(16) float Bs[32][128];   // [k][n]
    const int m0 = blockIdx.x * 64;
    const int n0 = blockIdx.y * 128;
    const int tid = threadIdx.x;
    const int tx = tid & 31, ty = tid >> 5;

    float4 acc[8];
#pragma unroll
    for (int r = 0; r < 8; r++) acc[r] = make_float4(0.f, 0.f, 0.f, 0.f);

    for (int kt = 0; kt < 128; kt += 32) {
        // load X tile 64x32 (as float4), store transposed
#pragma unroll
        for (int i = 0; i < 2; i++) {
            int lin = tid + i * 256;          // 0..511
            int m = lin >> 3, k4 = lin & 7;
            float4 v = reinterpret_cast<const float4*>(X)[(size_t)(m0 + m) * 32 + (kt >> 2) + k4];
            As[k4 * 4 + 0][m] = v.x; As[k4 * 4 + 1][m] = v.y;
            As[k4 * 4 + 2][m] = v.z; As[k4 * 4 + 3][m] = v.w;
        }
        // load W tile 32x128
#pragma unroll
        for (int i = 0; i < 4; i++) {
            int lin = tid + i * 256;          // 0..1023
            int k = lin >> 5, n4 = lin & 31;
            reinterpret_cast<float4*>(&Bs[k][0])[n4] =
                reinterpret_cast<const float4*>(Wm)[(size_t)(kt + k) * 256 + (n0 >> 2) + n4];
        }
        __syncthreads();
#pragma unroll
        for (int k = 0; k < 32; k++) {
            float4 b4 = reinterpret_cast<float4*>(&Bs[k][0])[tx];
            const float4* Ap = reinterpret_cast<const float4*>(&As[k][ty * 8]);
            float4 a0 = Ap[0], a1 = Ap[1];
            float am[8] = {a0.x, a0.y, a0.z, a0.w, a1.x, a1.y, a1.z, a1.w};
#pragma unroll
            for (int r = 0; r < 8; r++) {
                acc[r].x += am[r] * b4.x; acc[r].y += am[r] * b4.y;
                acc[r].z += am[r] * b4.z; acc[r].w += am[r] * b4.w;
            }
        }
        __syncthreads();
    }
    float4 bv = reinterpret_cast<const float4*>(bias)[(n0 >> 2) + tx];
#pragma unroll
    for (int r = 0; r < 8; r++) {
        int m = m0 + ty * 8 + r;
        float4 o = acc[r];
        o.x += bv.x; o.y += bv.y; o.z += bv.z; o.w += bv.w;
        reinterpret_cast<float4*>(g_G)[(size_t)m * 256 + (n0 >> 2) + tx] = o;
    }
}

// ---------------- phase B: persistent recurrent kernel -------------------
__device__ __forceinline__ float sigf(float x) { return 1.0f / (1.0f + __expf(-x)); }

__device__ __forceinline__ unsigned ld_acq(const unsigned* p) {
    unsigned v;
    asm volatile("ld.global.acquire.gpu.u32 %0, [%1];" : "=r"(v) : "l"(p) : "memory");
    return v;
}

// 128 CTAs = 16 groups (8 batches) x 8 h-slices (32 h-units = 128 gate cols).
// U slice register-resident for the whole sequence. c/h carries in registers.
__global__ __launch_bounds__(256, 1) void plstm_rec(
    const float* __restrict__ U, const float* __restrict__ ts,
    const float* __restrict__ Per, const float* __restrict__ Shf,
    const float* __restrict__ Oe, float* __restrict__ out, int writeTails) {
    __shared__ __align__(16) float hs_sm[8 * 256];  // staged h for 8 batches
    __shared__ __align__(16) float red[8192];       // [kc][b][j][g] partials

    const int tid = threadIdx.x;
    const int grp = blockIdx.x >> 3;
    const int hslc = blockIdx.x & 7;
    const int bg0 = grp * 8;
    const int hs = hslc * 32;
    const int kc = tid >> 5;     // matmul role: K-chunk (also = warp id)
    const int jj = tid & 31;     // matmul role: h-unit in slice
    const int ob = kc;           // owner role: batch in group
    const int oj = jj;           // owner role: h-unit in slice
    const int jg = hs + oj;

    // per-owner phased-gate constants
    const float pv = fabsf(Per[jg]);
    const float sv = Shf[jg];
    const float oe = fabsf(Oe[jg]);
    const float on_end = oe * pv;
    const float on_mid = (oe * 0.5f) * pv;

    // register-resident U slice: U[kc*32 + kk][g*256 + hs + jj]
    float Ureg[32][4];
    {
        const float* Ub = U + (size_t)(kc * 32) * 1024 + hs + jj;
#pragma unroll
        for (int kk = 0; kk < 32; kk++)
#pragma unroll
            for (int g = 0; g < 4; g++)
                Ureg[kk][g] = Ub[(size_t)kk * 1024 + g * 256];
    }

    float ccar = 0.f, hcar = 0.f;
    const float* tsrow = ts + (size_t)(bg0 + ob) * S_;
    const float* Gbase = g_G + (size_t)(bg0 + ob) * S_ * 1024 + hs + oj;

    for (int s = 0; s < S_; s++) {
        const int cur = s & 1, nxt = cur ^ 1;

        // prefetch owner inputs early (consumed after the FMA block)
        const float* Gp = Gbase + (size_t)s * 1024;
        float Gi = Gp[0], Gf = Gp[256], Gg = Gp[512], Go = Gp[768];
        float tt = tsrow[s];

        // stage h (L2-coherent reads, bypass L1)
        const float4* hbp = reinterpret_cast<const float4*>(&g_hbuf[cur][bg0 * H_]);
        float4* hsp = reinterpret_cast<float4*>(hs_sm);
        hsp[tid]       = __ldcg(hbp + tid);
        hsp[tid + 256] = __ldcg(hbp + tid + 256);
        __syncthreads();

        // matmul partials: 8 batches x 4 gates over this thread's 32 K values
        float acc[8][4];
#pragma unroll
        for (int b = 0; b < 8; b++) {
            acc[b][0] = 0.f; acc[b][1] = 0.f; acc[b][2] = 0.f; acc[b][3] = 0.f;
        }
#pragma unroll
        for (int b = 0; b < 8; b++) {
            const float4* hp = reinterpret_cast<const float4*>(&hs_sm[b * 256 + kc * 32]);
#pragma unroll
            for (int k4 = 0; k4 < 8; k4++) {
                float4 h4 = hp[k4];
                const int kk = k4 * 4;
#pragma unroll
                for (int g = 0; g < 4; g++) {
                    acc[b][g] += h4.x * Ureg[kk + 0][g];
                    acc[b][g] += h4.y * Ureg[kk + 1][g];
                    acc[b][g] += h4.z * Ureg[kk + 2][g];
                    acc[b][g] += h4.w * Ureg[kk + 3][g];
                }
            }
        }

        // write partials, reduce across 8 K-chunks
#pragma unroll
        for (int b = 0; b < 8; b++)
            reinterpret_cast<float4*>(red)[(kc * 8 + b) * 32 + jj] =
                make_float4(acc[b][0], acc[b][1], acc[b][2], acc[b][3]);
        __syncthreads();

        float4 sum = make_float4(0.f, 0.f, 0.f, 0.f);
#pragma unroll
        for (int q = 0; q < 8; q++) {
            float4 p = reinterpret_cast<const float4*>(red)[(q * 8 + ob) * 32 + oj];
            sum.x += p.x; sum.y += p.y; sum.z += p.z; sum.w += p.w;
        }

        // LSTM cell + phased time gate (owner thread owns (b, j) carries)
        float it = sigf(Gi + sum.x);
        float ft = sigf(Gf + sum.y);
        float gt = tanhf(Gg + sum.z);
        float ot = sigf(Go + sum.w);
        float cn = ft * ccar + it * gt;
        float hn = ot * tanhf(cn);

        float ic = fmodf(tt + sv, pv);
        float mask;
        if (ic <= on_mid)      mask = ic / on_mid;
        else if (ic <= on_end) mask = (on_end - ic) / on_mid;
        else                   mask = OFF_SLOPE * (ic / pv);

        ccar = mask * cn + (1.f - mask) * ccar;
        float h2 = mask * hn + (1.f - mask) * hcar;
        hcar = h2;

        out[((size_t)(bg0 + ob) * S_ + s) * H_ + jg] = h2;
        g_hbuf[nxt][(bg0 + ob) * H_ + jg] = h2;

        // group barrier (8 CTAs, sense-free monotonic counter)
        __syncthreads();
        if (tid == 0) {
            __threadfence();
            atomicAdd(&g_cnt[grp], 1u);
            const unsigned tgt = 8u * (unsigned)(s + 1);
            while (ld_acq(&g_cnt[grp]) < tgt) {}
        }
        __syncthreads();
    }

    if (writeTails) {
        const size_t baseT = (size_t)B_ * S_ * H_;
        out[baseT + (size_t)(bg0 + ob) * H_ + jg] = hcar;                          // h_T
        out[baseT + (size_t)B_ * H_ + (size_t)(bg0 + ob) * H_ + jg] = ccar;        // c_T
    }
}

// ---------------- launch ----------------
extern "C" void kernel_launch(void* const* d_in, const int* in_sizes, int n_in,
                              void* d_out, int out_size) {
    const float* x    = (const float*)d_in[0];
    const float* ts   = (const float*)d_in[1];
    const float* W    = (const float*)d_in[2];
    const float* U    = (const float*)d_in[3];
    const float* bias = (const float*)d_in[4];
    const float* Per  = (const float*)d_in[5];
    const float* Shf  = (const float*)d_in[6];
    const float* Oe   = (const float*)d_in[7];
    float* out = (float*)d_out;

    init_k<<<64, 256>>>();

    dim3 gg(131072 / 64, 1024 / 128);
    gemm_xw<<<gg, 256>>>(x, W, bias);

    const long long need = (long long)B_ * S_ * H_ + 2LL * B_ * H_;
    int writeTails = ((long long)out_size >= need) ? 1 : 0;
    plstm_rec<<<128, 256>>>(U, ts, Per, Shf, Oe, out, writeTails);
}